// round 12
// baseline (speedup 1.0000x reference)
#include <cuda_runtime.h>
#include <cuda_bf16.h>

#define NPART 2048
#define HID 32
#define CUTOFF 2.5f
#define CUTOFF2 6.25f
#define NTHREADS 128
#define NWARPS 4
#define M_TAB 2048

__device__ double g_energy_accum = 0.0;
__device__ unsigned int g_block_count = 0;
__device__ float g_table[M_TAB + 1];
__device__ float4 g_pos[NPART];

// Build energy table e(d) (exact tanhf) + pack coordinates into float4.
__global__ void __launch_bounds__(256) pp_table_kernel(
    const float* __restrict__ xyz,
    const float* __restrict__ W1,
    const float* __restrict__ b1,
    const float* __restrict__ W2,
    const float* __restrict__ b2)
{
    const int t = blockIdx.x * blockDim.x + threadIdx.x;

    if (t <= M_TAB) {
        const float d = (CUTOFF / (float)M_TAB) * (float)t;
        float e = __ldg(&b2[0]);
        #pragma unroll
        for (int k = 0; k < HID; ++k) {
            e = fmaf(__ldg(&W2[k]), tanhf(fmaf(d, __ldg(&W1[k]), __ldg(&b1[k]))), e);
        }
        g_table[t] = e;
    }

    if (t < NPART) {
        g_pos[t] = make_float4(xyz[3 * t + 0], xyz[3 * t + 1], xyz[3 * t + 2], 0.0f);
    }
}

__global__ void __launch_bounds__(NTHREADS) pp_pair_kernel(
    const float* __restrict__ cell_diag,
    float* __restrict__ out)
{
    __shared__ float sRed[NWARPS];

    const int tid  = threadIdx.x;
    const int warp = tid >> 5;
    const int lane = tid & 31;

    const float Lx = __ldg(&cell_diag[0]);
    const float Ly = __ldg(&cell_diag[1]);
    const float Lz = __ldg(&cell_diag[2]);
    const float iLx = __frcp_rn(Lx), iLy = __frcp_rn(Ly), iLz = __frcp_rn(Lz);
    const float tscale = (float)M_TAB / CUTOFF;

    float acc = 0.0f;

    // 2 blocks per balanced row-pair: block = 2*ipair + half
    const int ipair = (int)(blockIdx.x >> 1);
    const int half  = (int)(blockIdx.x & 1);
    const int vwarp = half * NWARPS + warp;        // 0..7
    const int rows[2] = { ipair, NPART - 1 - ipair };

    #pragma unroll
    for (int r = 0; r < 2; ++r) {
        const int i = rows[r];
        const float4 pi = g_pos[i];

        // each vwarp covers 64 j's per iteration (2 per lane), 8 vwarps => stride 512
        for (int base = i + 1 + vwarp * 64; base < NPART; base += 512) {
            const int j0 = base + lane;
            const int j1 = base + 32 + lane;
            const int jc0 = (j0 < NPART) ? j0 : (NPART - 1);
            const int jc1 = (j1 < NPART) ? j1 : (NPART - 1);

            const float4 p0 = g_pos[jc0];
            const float4 p1 = g_pos[jc1];

            // chain 0
            float dx0 = p0.x - pi.x, dy0 = p0.y - pi.y, dz0 = p0.z - pi.z;
            dx0 = fmaf(-Lx, rintf(dx0 * iLx), dx0);
            dy0 = fmaf(-Ly, rintf(dy0 * iLy), dy0);
            dz0 = fmaf(-Lz, rintf(dz0 * iLz), dz0);
            const float r20 = fmaf(dx0, dx0, fmaf(dy0, dy0, dz0 * dz0));

            // chain 1 (independent)
            float dx1 = p1.x - pi.x, dy1 = p1.y - pi.y, dz1 = p1.z - pi.z;
            dx1 = fmaf(-Lx, rintf(dx1 * iLx), dx1);
            dy1 = fmaf(-Ly, rintf(dy1 * iLy), dy1);
            dz1 = fmaf(-Lz, rintf(dz1 * iLz), dz1);
            const float r21 = fmaf(dx1, dx1, fmaf(dy1, dy1, dz1 * dz1));

            if (r20 < CUTOFF2 && r20 > 0.0f && j0 < NPART) {
                const float u = sqrtf(r20) * tscale;
                const int   t = (int)u;
                const float f = u - (float)t;
                const float e0 = g_table[t];
                const float e1 = g_table[t + 1];
                acc += fmaf(e1 - e0, f, e0);
            }
            if (r21 < CUTOFF2 && r21 > 0.0f && j1 < NPART) {
                const float u = sqrtf(r21) * tscale;
                const int   t = (int)u;
                const float f = u - (float)t;
                const float e0 = g_table[t];
                const float e1 = g_table[t + 1];
                acc += fmaf(e1 - e0, f, e0);
            }
        }
    }

    // block reduction
    #pragma unroll
    for (int off = 16; off > 0; off >>= 1)
        acc += __shfl_xor_sync(0xFFFFFFFFu, acc, off);
    if (lane == 0) sRed[warp] = acc;
    __syncthreads();

    if (tid == 0) {
        const float bsum = sRed[0] + sRed[1] + sRed[2] + sRed[3];
        atomicAdd(&g_energy_accum, (double)bsum);
        __threadfence();
        const unsigned int ticket = atomicAdd(&g_block_count, 1u);
        if (ticket == gridDim.x - 1) {
            const double total = atomicAdd(&g_energy_accum, 0.0);
            out[0] = (float)total;
            g_energy_accum = 0.0;
            g_block_count = 0;
            __threadfence();
        }
    }
}

extern "C" void kernel_launch(void* const* d_in, const int* in_sizes, int n_in,
                              void* d_out, int out_size) {
    const float* xyz       = (const float*)d_in[0];
    const float* cell_diag = (const float*)d_in[1];
    const float* W1        = (const float*)d_in[2];
    const float* b1        = (const float*)d_in[3];
    const float* W2        = (const float*)d_in[4];
    const float* b2        = (const float*)d_in[5];
    float* out = (float*)d_out;

    // 2049 table entries + 2048 pos packs: 9 blocks x 256 = 2304 threads covers both
    pp_table_kernel<<<9, 256>>>(xyz, W1, b1, W2, b2);
    pp_pair_kernel<<<NPART, NTHREADS>>>(cell_diag, out);
}